// round 6
// baseline (speedup 1.0000x reference)
#include <cuda_runtime.h>
#include <math.h>

#define BN   8
#define NN   16384
#define DD   768
#define RR   3
#define NEXP 4
#define HH   128

// ---------------- scratch (device globals; no allocation allowed) ----------------
__device__ float g_xr[BN * RR * NN];     // feat layout: [(b*3+r)*16384 + n], n = y*128+x
__device__ float g_mx[BN * RR * NN];     // mixed, same layout
__device__ float g_part[4096 * 3];       // per-block partial sums for the mean
__device__ float g_G[BN * NEXP];

// ---------------- pass 1: xr = x @ Wd + bd  (4 rows per warp) --------------------
__global__ void __launch_bounds__(256)
k_xr(const float* __restrict__ x, const float* __restrict__ Wd,
     const float* __restrict__ bd)
{
    __shared__ float4 sW[3][192];     // Wd transposed: sW[r][e4]
    __shared__ float  sPart[8][3];
    int tid = threadIdx.x;
    float* sWf = (float*)sW;
    for (int i = tid; i < DD * RR; i += 256) {
        int r = i / DD, e = i % DD;
        sWf[r * DD + e] = Wd[e * RR + r];
    }
    __syncthreads();

    int warp = tid >> 5, lane = tid & 31;
    // block covers 32 consecutive rows; warp covers 4
    long long row0 = (long long)blockIdx.x * 32 + warp * 4;
    const float4* x4 = (const float4*)x + row0 * 192;

    float a[4][3];
#pragma unroll
    for (int rr = 0; rr < 4; rr++) { a[rr][0] = 0.f; a[rr][1] = 0.f; a[rr][2] = 0.f; }

#pragma unroll
    for (int i = 0; i < 6; i++) {
        int j = i * 32 + lane;
        float4 xv[4];
#pragma unroll
        for (int rr = 0; rr < 4; rr++) xv[rr] = x4[rr * 192 + j];   // 4 batched LDG.128
        float4 w0 = sW[0][j], w1 = sW[1][j], w2 = sW[2][j];
#pragma unroll
        for (int rr = 0; rr < 4; rr++) {
            a[rr][0] = fmaf(xv[rr].x, w0.x, fmaf(xv[rr].y, w0.y, fmaf(xv[rr].z, w0.z, fmaf(xv[rr].w, w0.w, a[rr][0]))));
            a[rr][1] = fmaf(xv[rr].x, w1.x, fmaf(xv[rr].y, w1.y, fmaf(xv[rr].z, w1.z, fmaf(xv[rr].w, w1.w, a[rr][1]))));
            a[rr][2] = fmaf(xv[rr].x, w2.x, fmaf(xv[rr].y, w2.y, fmaf(xv[rr].z, w2.z, fmaf(xv[rr].w, w2.w, a[rr][2]))));
        }
    }
#pragma unroll
    for (int rr = 0; rr < 4; rr++)
#pragma unroll
        for (int c = 0; c < 3; c++)
#pragma unroll
            for (int o = 16; o; o >>= 1)
                a[rr][c] += __shfl_down_sync(0xffffffffu, a[rr][c], o);

    if (lane == 0) {
        float p0 = 0.f, p1 = 0.f, p2 = 0.f;
#pragma unroll
        for (int rr = 0; rr < 4; rr++) {
            long long row = row0 + rr;
            int b = (int)(row >> 14);
            int n = (int)(row & 16383);
            float v0 = a[rr][0] + bd[0];
            float v1 = a[rr][1] + bd[1];
            float v2 = a[rr][2] + bd[2];
            g_xr[(b * 3 + 0) * NN + n] = v0;
            g_xr[(b * 3 + 1) * NN + n] = v1;
            g_xr[(b * 3 + 2) * NN + n] = v2;
            p0 += v0; p1 += v1; p2 += v2;
        }
        sPart[warp][0] = p0; sPart[warp][1] = p1; sPart[warp][2] = p2;
    }
    __syncthreads();
    if (tid < 3) {
        float s = 0.f;
#pragma unroll
        for (int w = 0; w < 8; w++) s += sPart[w][tid];
        g_part[blockIdx.x * 3 + tid] = s;   // block's 32 rows all share one b
    }
}

// ---------------- helpers --------------------------------------------------------
__device__ __forceinline__ float bilin(const float* __restrict__ src, int ih, int iw,
                                       float sy, float sx)
{
    int y0 = (int)floorf(sy); float fy = sy - y0;
    int x0 = (int)floorf(sx); float fx = sx - x0;
    int y0c = min(max(y0, 0), ih - 1), y1c = min(max(y0 + 1, 0), ih - 1);
    int x0c = min(max(x0, 0), iw - 1), x1c = min(max(x0 + 1, 0), iw - 1);
    return (1.f - fy) * ((1.f - fx) * src[y0c * iw + x0c] + fx * src[y0c * iw + x1c])
         +        fy  * ((1.f - fx) * src[y1c * iw + x0c] + fx * src[y1c * iw + x1c]);
}

__device__ __forceinline__ float conv3x3(const float* __restrict__ src, int h, int w,
                                         int y, int xp, const float* __restrict__ k9,
                                         float bias)
{
    float acc = bias;
#pragma unroll
    for (int dy = -1; dy <= 1; dy++) {
        int yy = y + dy;
        if (yy < 0 || yy >= h) continue;
#pragma unroll
        for (int dx = -1; dx <= 1; dx++) {
            int xx = xp + dx;
            if (xx < 0 || xx >= w) continue;
            acc = fmaf(src[yy * w + xx], k9[(dy + 1) * 3 + (dx + 1)], acc);
        }
    }
    return acc;
}

// ---------------- fused pyramid: gating + all scales, one block per (b,r) plane --
__global__ void __launch_bounds__(512, 1)
k_pyr(const float* __restrict__ noise, const float* __restrict__ Wg,
      const float* __restrict__ Wn, const float* __restrict__ dwk,
      const float* __restrict__ dwb)
{
    __shared__ float sD64[64 * 64], sC64[64 * 64];
    __shared__ float sD32[32 * 32], sC32[32 * 32];
    __shared__ float sD16[16 * 16], sC16[16 * 16];
    __shared__ float sXa[3], sG[NEXP], sK[9], sBias[1];

    int p = blockIdx.x;            // 0..23
    int b = p / 3, r = p % 3;
    int tid = threadIdx.x;
    int warp = tid >> 5, lane = tid & 31;

    // --- gating: redundant per-block deterministic reduce over g_part (this b) ---
    // 512 k_xr blocks per batch
    if (warp < 3) {
        float s = 0.f;
        for (int k = lane; k < 512; k += 32)
            s += g_part[(b * 512 + k) * 3 + warp];
#pragma unroll
        for (int o = 16; o; o >>= 1) s += __shfl_down_sync(0xffffffffu, s, o);
        if (lane == 0) sXa[warp] = s * (1.0f / 16384.0f);
    }
    if (warp == 3) {
        if (lane < 9) sK[lane] = dwk[r * 9 + lane];
        if (lane == 9) sBias[0] = dwb[r];
    }
    __syncthreads();
    if (tid == 0) {
        float v[NEXP];
#pragma unroll
        for (int e = 0; e < NEXP; e++) {
            float hg = 0.f, hn = 0.f;
#pragma unroll
            for (int rr = 0; rr < RR; rr++) {
                hg = fmaf(sXa[rr], Wg[rr * NEXP + e], hg);
                hn = fmaf(sXa[rr], Wn[rr * NEXP + e], hn);
            }
            float sp = fmaxf(hn, 0.f) + log1pf(expf(-fabsf(hn)));  // stable softplus
            v[e] = hg + noise[b * NEXP + e] * sp;
        }
        int i1 = 0;
        for (int e = 1; e < NEXP; e++) if (v[e] > v[i1]) i1 = e;   // first-occurrence ties
        int i2 = -1;
        for (int e = 0; e < NEXP; e++) {
            if (e == i1) continue;
            if (i2 < 0 || v[e] > v[i2]) i2 = e;
        }
        float e2 = expf(v[i2] - v[i1]);
        float inv = 1.0f / (1.0f + e2);
#pragma unroll
        for (int e = 0; e < NEXP; e++) sG[e] = 0.f;
        sG[i1] = inv;
        sG[i2] = e2 * inv;
    }

    const float* __restrict__ plane = g_xr + p * NN;

    // --- downsample from full-res plane (L1/L2 resident) into smem ---
    for (int idx = tid; idx < 64 * 64; idx += 512) {
        int y = idx >> 6, xp = idx & 63;
        sD64[idx] = bilin(plane, HH, HH, (y + 0.5f) * 2.0f - 0.5f, (xp + 0.5f) * 2.0f - 0.5f);
    }
    for (int idx = tid; idx < 32 * 32; idx += 512) {
        int y = idx >> 5, xp = idx & 31;
        sD32[idx] = bilin(plane, HH, HH, (y + 0.5f) * 4.0f - 0.5f, (xp + 0.5f) * 4.0f - 0.5f);
    }
    for (int idx = tid; idx < 16 * 16; idx += 512) {
        int y = idx >> 4, xp = idx & 15;
        sD16[idx] = bilin(plane, HH, HH, (y + 0.5f) * 8.0f - 0.5f, (xp + 0.5f) * 8.0f - 0.5f);
    }
    __syncthreads();

    // --- depthwise conv at each downsampled resolution (zero pad) ---
    float bias = sBias[0];
    for (int idx = tid; idx < 64 * 64; idx += 512)
        sC64[idx] = conv3x3(sD64, 64, 64, idx >> 6, idx & 63, sK, bias);
    for (int idx = tid; idx < 32 * 32; idx += 512)
        sC32[idx] = conv3x3(sD32, 32, 32, idx >> 5, idx & 31, sK, bias);
    for (int idx = tid; idx < 16 * 16; idx += 512)
        sC16[idx] = conv3x3(sD16, 16, 16, idx >> 4, idx & 15, sK, bias);
    __syncthreads();

    // --- full-res conv + upsample all scales + gated accumulate -> g_mx ---
    float G0 = sG[0], G1 = sG[1], G2 = sG[2], G3 = sG[3];
    float* __restrict__ outp = g_mx + p * NN;
    for (int idx = tid; idx < NN; idx += 512) {
        int y = idx >> 7, xp = idx & 127;
        float cf = conv3x3(plane, HH, HH, y, xp, sK, bias);
        float u1 = bilin(sC64, 64, 64, (y + 0.5f) * 0.5f   - 0.5f, (xp + 0.5f) * 0.5f   - 0.5f);
        float u2 = bilin(sC32, 32, 32, (y + 0.5f) * 0.25f  - 0.5f, (xp + 0.5f) * 0.25f  - 0.5f);
        float u3 = bilin(sC16, 16, 16, (y + 0.5f) * 0.125f - 0.5f, (xp + 0.5f) * 0.125f - 0.5f);
        outp[idx] = fmaf(G0, cf, fmaf(G1, u1, fmaf(G2, u2, G3 * u3)));
    }
}

// ---------------- pass 4: out = x + mixed @ Wu + bu  (2 rows per warp) -----------
__global__ void __launch_bounds__(256)
k_out(const float* __restrict__ x, const float* __restrict__ Wu,
      const float* __restrict__ bu, float* __restrict__ out)
{
    __shared__ float4 sU[3][192];
    __shared__ float4 sB[192];
    int tid = threadIdx.x;
    float* sUf = (float*)sU;
    float* sBf = (float*)sB;
    for (int i = tid; i < DD * RR; i += 256) sUf[i] = Wu[i];  // Wu is (3,768) row-major
    for (int i = tid; i < DD; i += 256) sBf[i] = bu[i];
    __syncthreads();

    int warp = tid >> 5, lane = tid & 31;
    long long row0 = (long long)blockIdx.x * 16 + warp * 2;   // 16 rows per block
    int b = (int)(row0 >> 14);
    int n0 = (int)(row0 & 16383);
    int n1 = n0 + 1;                                          // same b (16-row aligned)
    float m00 = g_mx[(b * 3 + 0) * NN + n0];   // warp-uniform -> broadcast
    float m01 = g_mx[(b * 3 + 1) * NN + n0];
    float m02 = g_mx[(b * 3 + 2) * NN + n0];
    float m10 = g_mx[(b * 3 + 0) * NN + n1];
    float m11 = g_mx[(b * 3 + 1) * NN + n1];
    float m12 = g_mx[(b * 3 + 2) * NN + n1];
    const float4* xA = (const float4*)x + row0 * 192;
    const float4* xB = xA + 192;
    float4* oA = (float4*)out + row0 * 192;
    float4* oB = oA + 192;
#pragma unroll
    for (int i = 0; i < 6; i++) {
        int j = i * 32 + lane;
        float4 xvA = xA[j];
        float4 xvB = xB[j];
        float4 u0 = sU[0][j], u1 = sU[1][j], u2 = sU[2][j], bv = sB[j];
        float4 o;
        o.x = fmaf(m02, u2.x, fmaf(m01, u1.x, fmaf(m00, u0.x, xvA.x + bv.x)));
        o.y = fmaf(m02, u2.y, fmaf(m01, u1.y, fmaf(m00, u0.y, xvA.y + bv.y)));
        o.z = fmaf(m02, u2.z, fmaf(m01, u1.z, fmaf(m00, u0.z, xvA.z + bv.z)));
        o.w = fmaf(m02, u2.w, fmaf(m01, u1.w, fmaf(m00, u0.w, xvA.w + bv.w)));
        oA[j] = o;
        o.x = fmaf(m12, u2.x, fmaf(m11, u1.x, fmaf(m10, u0.x, xvB.x + bv.x)));
        o.y = fmaf(m12, u2.y, fmaf(m11, u1.y, fmaf(m10, u0.y, xvB.y + bv.y)));
        o.z = fmaf(m12, u2.z, fmaf(m11, u1.z, fmaf(m10, u0.z, xvB.z + bv.z)));
        o.w = fmaf(m12, u2.w, fmaf(m11, u1.w, fmaf(m10, u0.w, xvB.w + bv.w)));
        oB[j] = o;
    }
}

// ---------------- launch ---------------------------------------------------------
extern "C" void kernel_launch(void* const* d_in, const int* in_sizes, int n_in,
                              void* d_out, int out_size)
{
    const float* x     = (const float*)d_in[0];
    const float* noise = (const float*)d_in[1];
    const float* Wd    = (const float*)d_in[2];
    const float* bd    = (const float*)d_in[3];
    const float* Wu    = (const float*)d_in[4];
    const float* bu    = (const float*)d_in[5];
    const float* Wg    = (const float*)d_in[6];
    const float* Wn    = (const float*)d_in[7];
    const float* dwk   = (const float*)d_in[8];
    const float* dwb   = (const float*)d_in[9];
    float* out = (float*)d_out;

    k_xr<<<4096, 256>>>(x, Wd, bd);
    k_pyr<<<24, 512>>>(noise, Wg, Wn, dwk, dwb);
    k_out<<<8192, 256>>>(x, Wu, bu, out);
}

// round 11
// speedup vs baseline: 1.0631x; 1.0631x over previous
#include <cuda_runtime.h>
#include <math.h>

#define BN   8
#define NN   16384
#define DD   768
#define RR   3
#define NEXP 4
#define HH   128

// ---------------- scratch (device globals; no allocation allowed) ----------------
__device__ float g_xr[BN * RR * NN];     // feat layout: [(b*3+r)*16384 + n], n = y*128+x
__device__ float g_mx[BN * RR * NN];     // mixed, same layout
__device__ float g_part[8192 * 3];       // per-block partial sums for the mean

// ---------------- pass 1: xr = x @ Wd + bd  (2 rows per warp) --------------------
__global__ void __launch_bounds__(256)
k_xr(const float* __restrict__ x, const float* __restrict__ Wd,
     const float* __restrict__ bd)
{
    __shared__ float4 sW[3][192];     // Wd transposed: sW[r][e4]
    __shared__ float  sPart[8][3];
    int tid = threadIdx.x;
    float* sWf = (float*)sW;
    for (int i = tid; i < DD * RR; i += 256) {
        int r = i / DD, e = i % DD;
        sWf[r * DD + e] = Wd[e * RR + r];
    }
    __syncthreads();

    int warp = tid >> 5, lane = tid & 31;
    // block covers 16 consecutive rows; warp covers 2
    long long row0 = (long long)blockIdx.x * 16 + warp * 2;
    const float4* x4 = (const float4*)x + row0 * 192;

    float a00 = 0.f, a01 = 0.f, a02 = 0.f;
    float a10 = 0.f, a11 = 0.f, a12 = 0.f;

#pragma unroll
    for (int i = 0; i < 6; i++) {
        int j = i * 32 + lane;
        float4 xv0 = x4[j];            // 2 batched LDG.128
        float4 xv1 = x4[192 + j];
        float4 w0 = sW[0][j], w1 = sW[1][j], w2 = sW[2][j];
        a00 = fmaf(xv0.x, w0.x, fmaf(xv0.y, w0.y, fmaf(xv0.z, w0.z, fmaf(xv0.w, w0.w, a00))));
        a01 = fmaf(xv0.x, w1.x, fmaf(xv0.y, w1.y, fmaf(xv0.z, w1.z, fmaf(xv0.w, w1.w, a01))));
        a02 = fmaf(xv0.x, w2.x, fmaf(xv0.y, w2.y, fmaf(xv0.z, w2.z, fmaf(xv0.w, w2.w, a02))));
        a10 = fmaf(xv1.x, w0.x, fmaf(xv1.y, w0.y, fmaf(xv1.z, w0.z, fmaf(xv1.w, w0.w, a10))));
        a11 = fmaf(xv1.x, w1.x, fmaf(xv1.y, w1.y, fmaf(xv1.z, w1.z, fmaf(xv1.w, w1.w, a11))));
        a12 = fmaf(xv1.x, w2.x, fmaf(xv1.y, w2.y, fmaf(xv1.z, w2.z, fmaf(xv1.w, w2.w, a12))));
    }
#pragma unroll
    for (int o = 16; o; o >>= 1) {
        a00 += __shfl_down_sync(0xffffffffu, a00, o);
        a01 += __shfl_down_sync(0xffffffffu, a01, o);
        a02 += __shfl_down_sync(0xffffffffu, a02, o);
        a10 += __shfl_down_sync(0xffffffffu, a10, o);
        a11 += __shfl_down_sync(0xffffffffu, a11, o);
        a12 += __shfl_down_sync(0xffffffffu, a12, o);
    }

    if (lane == 0) {
        int b = (int)(row0 >> 14);          // both rows share b (16-row aligned blocks)
        int n0 = (int)(row0 & 16383);
        float v00 = a00 + bd[0], v01 = a01 + bd[1], v02 = a02 + bd[2];
        float v10 = a10 + bd[0], v11 = a11 + bd[1], v12 = a12 + bd[2];
        g_xr[(b * 3 + 0) * NN + n0]     = v00;
        g_xr[(b * 3 + 1) * NN + n0]     = v01;
        g_xr[(b * 3 + 2) * NN + n0]     = v02;
        g_xr[(b * 3 + 0) * NN + n0 + 1] = v10;
        g_xr[(b * 3 + 1) * NN + n0 + 1] = v11;
        g_xr[(b * 3 + 2) * NN + n0 + 1] = v12;
        sPart[warp][0] = v00 + v10;
        sPart[warp][1] = v01 + v11;
        sPart[warp][2] = v02 + v12;
    }
    __syncthreads();
    if (tid < 3) {
        float s = 0.f;
#pragma unroll
        for (int w = 0; w < 8; w++) s += sPart[w][tid];
        g_part[blockIdx.x * 3 + tid] = s;   // block's 16 rows all share one b
    }
}

// ---------------- helpers --------------------------------------------------------
__device__ __forceinline__ float bilin(const float* __restrict__ src, int ih, int iw,
                                       float sy, float sx)
{
    int y0 = (int)floorf(sy); float fy = sy - y0;
    int x0 = (int)floorf(sx); float fx = sx - x0;
    int y0c = min(max(y0, 0), ih - 1), y1c = min(max(y0 + 1, 0), ih - 1);
    int x0c = min(max(x0, 0), iw - 1), x1c = min(max(x0 + 1, 0), iw - 1);
    return (1.f - fy) * ((1.f - fx) * src[y0c * iw + x0c] + fx * src[y0c * iw + x1c])
         +        fy  * ((1.f - fx) * src[y1c * iw + x0c] + fx * src[y1c * iw + x1c]);
}

__device__ __forceinline__ float conv3x3(const float* __restrict__ src, int h, int w,
                                         int y, int xp, const float* __restrict__ k9,
                                         float bias)
{
    float acc = bias;
#pragma unroll
    for (int dy = -1; dy <= 1; dy++) {
        int yy = y + dy;
        if (yy < 0 || yy >= h) continue;
#pragma unroll
        for (int dx = -1; dx <= 1; dx++) {
            int xx = xp + dx;
            if (xx < 0 || xx >= w) continue;
            acc = fmaf(src[yy * w + xx], k9[(dy + 1) * 3 + (dx + 1)], acc);
        }
    }
    return acc;
}

// ---------------- fused pyramid: gating + all scales, one block per (b,r) plane --
__global__ void __launch_bounds__(512, 1)
k_pyr(const float* __restrict__ noise, const float* __restrict__ Wg,
      const float* __restrict__ Wn, const float* __restrict__ dwk,
      const float* __restrict__ dwb)
{
    __shared__ float sD64[64 * 64], sC64[64 * 64];
    __shared__ float sD32[32 * 32], sC32[32 * 32];
    __shared__ float sD16[16 * 16], sC16[16 * 16];
    __shared__ float sXa[3], sG[NEXP], sK[9], sBias[1];

    int p = blockIdx.x;            // 0..23
    int b = p / 3, r = p % 3;
    int tid = threadIdx.x;
    int warp = tid >> 5, lane = tid & 31;

    // --- gating: redundant per-block deterministic reduce over g_part (this b) ---
    // 1024 k_xr blocks per batch
    if (warp < 3) {
        float s = 0.f;
        for (int k = lane; k < 1024; k += 32)
            s += g_part[(b * 1024 + k) * 3 + warp];
#pragma unroll
        for (int o = 16; o; o >>= 1) s += __shfl_down_sync(0xffffffffu, s, o);
        if (lane == 0) sXa[warp] = s * (1.0f / 16384.0f);
    }
    if (warp == 3) {
        if (lane < 9) sK[lane] = dwk[r * 9 + lane];
        if (lane == 9) sBias[0] = dwb[r];
    }
    __syncthreads();
    if (tid == 0) {
        float v[NEXP];
#pragma unroll
        for (int e = 0; e < NEXP; e++) {
            float hg = 0.f, hn = 0.f;
#pragma unroll
            for (int rr = 0; rr < RR; rr++) {
                hg = fmaf(sXa[rr], Wg[rr * NEXP + e], hg);
                hn = fmaf(sXa[rr], Wn[rr * NEXP + e], hn);
            }
            float sp = fmaxf(hn, 0.f) + log1pf(expf(-fabsf(hn)));  // stable softplus
            v[e] = hg + noise[b * NEXP + e] * sp;
        }
        int i1 = 0;
        for (int e = 1; e < NEXP; e++) if (v[e] > v[i1]) i1 = e;   // first-occurrence ties
        int i2 = -1;
        for (int e = 0; e < NEXP; e++) {
            if (e == i1) continue;
            if (i2 < 0 || v[e] > v[i2]) i2 = e;
        }
        float e2 = expf(v[i2] - v[i1]);
        float inv = 1.0f / (1.0f + e2);
#pragma unroll
        for (int e = 0; e < NEXP; e++) sG[e] = 0.f;
        sG[i1] = inv;
        sG[i2] = e2 * inv;
    }

    const float* __restrict__ plane = g_xr + p * NN;

    // --- downsample from full-res plane (L1/L2 resident) into smem ---
    for (int idx = tid; idx < 64 * 64; idx += 512) {
        int y = idx >> 6, xp = idx & 63;
        sD64[idx] = bilin(plane, HH, HH, (y + 0.5f) * 2.0f - 0.5f, (xp + 0.5f) * 2.0f - 0.5f);
    }
    for (int idx = tid; idx < 32 * 32; idx += 512) {
        int y = idx >> 5, xp = idx & 31;
        sD32[idx] = bilin(plane, HH, HH, (y + 0.5f) * 4.0f - 0.5f, (xp + 0.5f) * 4.0f - 0.5f);
    }
    for (int idx = tid; idx < 16 * 16; idx += 512) {
        int y = idx >> 4, xp = idx & 15;
        sD16[idx] = bilin(plane, HH, HH, (y + 0.5f) * 8.0f - 0.5f, (xp + 0.5f) * 8.0f - 0.5f);
    }
    __syncthreads();

    // --- depthwise conv at each downsampled resolution (zero pad) ---
    float bias = sBias[0];
    for (int idx = tid; idx < 64 * 64; idx += 512)
        sC64[idx] = conv3x3(sD64, 64, 64, idx >> 6, idx & 63, sK, bias);
    for (int idx = tid; idx < 32 * 32; idx += 512)
        sC32[idx] = conv3x3(sD32, 32, 32, idx >> 5, idx & 31, sK, bias);
    for (int idx = tid; idx < 16 * 16; idx += 512)
        sC16[idx] = conv3x3(sD16, 16, 16, idx >> 4, idx & 15, sK, bias);
    __syncthreads();

    // --- full-res conv + upsample all scales + gated accumulate -> g_mx ---
    float G0 = sG[0], G1 = sG[1], G2 = sG[2], G3 = sG[3];
    float* __restrict__ outp = g_mx + p * NN;
    for (int idx = tid; idx < NN; idx += 512) {
        int y = idx >> 7, xp = idx & 127;
        float cf = conv3x3(plane, HH, HH, y, xp, sK, bias);
        float u1 = bilin(sC64, 64, 64, (y + 0.5f) * 0.5f   - 0.5f, (xp + 0.5f) * 0.5f   - 0.5f);
        float u2 = bilin(sC32, 32, 32, (y + 0.5f) * 0.25f  - 0.5f, (xp + 0.5f) * 0.25f  - 0.5f);
        float u3 = bilin(sC16, 16, 16, (y + 0.5f) * 0.125f - 0.5f, (xp + 0.5f) * 0.125f - 0.5f);
        outp[idx] = fmaf(G0, cf, fmaf(G1, u1, fmaf(G2, u2, G3 * u3)));
    }
}

// ---------------- pass 4: out = x + mixed @ Wu + bu  (1 row per warp, R4 form) ---
__global__ void __launch_bounds__(256)
k_out(const float* __restrict__ x, const float* __restrict__ Wu,
      const float* __restrict__ bu, float* __restrict__ out)
{
    __shared__ float4 sU[3][192];
    __shared__ float4 sB[192];
    int tid = threadIdx.x;
    float* sUf = (float*)sU;
    float* sBf = (float*)sB;
    for (int i = tid; i < DD * RR; i += 256) sUf[i] = Wu[i];  // Wu is (3,768) row-major
    for (int i = tid; i < DD; i += 256) sBf[i] = bu[i];
    __syncthreads();

    int warp = tid >> 5, lane = tid & 31;
    long long row = (long long)blockIdx.x * 8 + warp;
    int b = (int)(row >> 14), n = (int)(row & 16383);
    float m0 = g_mx[(b * 3 + 0) * NN + n];   // warp-uniform -> broadcast
    float m1 = g_mx[(b * 3 + 1) * NN + n];
    float m2 = g_mx[(b * 3 + 2) * NN + n];
    const float4* x4 = (const float4*)x + row * 192;
    float4* o4 = (float4*)out + row * 192;
#pragma unroll
    for (int i = 0; i < 6; i++) {
        int j = i * 32 + lane;
        float4 xv = x4[j];
        float4 u0 = sU[0][j], u1 = sU[1][j], u2 = sU[2][j], bv = sB[j];
        float4 o;
        o.x = fmaf(m2, u2.x, fmaf(m1, u1.x, fmaf(m0, u0.x, xv.x + bv.x)));
        o.y = fmaf(m2, u2.y, fmaf(m1, u1.y, fmaf(m0, u0.y, xv.y + bv.y)));
        o.z = fmaf(m2, u2.z, fmaf(m1, u1.z, fmaf(m0, u0.z, xv.z + bv.z)));
        o.w = fmaf(m2, u2.w, fmaf(m1, u1.w, fmaf(m0, u0.w, xv.w + bv.w)));
        o4[j] = o;
    }
}

// ---------------- launch ---------------------------------------------------------
extern "C" void kernel_launch(void* const* d_in, const int* in_sizes, int n_in,
                              void* d_out, int out_size)
{
    const float* x     = (const float*)d_in[0];
    const float* noise = (const float*)d_in[1];
    const float* Wd    = (const float*)d_in[2];
    const float* bd    = (const float*)d_in[3];
    const float* Wu    = (const float*)d_in[4];
    const float* bu    = (const float*)d_in[5];
    const float* Wg    = (const float*)d_in[6];
    const float* Wn    = (const float*)d_in[7];
    const float* dwk   = (const float*)d_in[8];
    const float* dwb   = (const float*)d_in[9];
    float* out = (float*)d_out;

    k_xr<<<8192, 256>>>(x, Wd, bd);
    k_pyr<<<24, 512>>>(noise, Wg, Wn, dwk, dwb);
    k_out<<<16384, 256>>>(x, Wu, bu, out);
}